// round 9
// baseline (speedup 1.0000x reference)
#include <cuda_runtime.h>
#include <cuda_fp16.h>
#include <cuda_bf16.h>

#define NN 50000
#define EE 800000
#define FI 128
#define HH 128
#define GG 256
#define TT 4

#define SCAN_BLKS 49   // ceil(12500 int4 / 256)

// ---------------- streams/events (created once at program init, before harness baseline) ----
struct SideStream {
    cudaStream_t s2;
    cudaEvent_t  evFork, evCsr;
    SideStream() {
        cudaStreamCreateWithFlags(&s2, cudaStreamNonBlocking);
        cudaEventCreateWithFlags(&evFork, cudaEventDisableTiming);
        cudaEventCreateWithFlags(&evCsr,  cudaEventDisableTiming);
    }
};
static SideStream g_ss;

// ---------------- scratch (device globals) ----------------
__device__ int    g_deg[NN];
__device__ int    g_rowptr[NN + 1];
__device__ int    g_pos[NN];
__device__ int    g_col[EE];
__device__ float  g_dinv[NN];
__device__ int    g_bsum[SCAN_BLKS];
__device__ int    g_boff[SCAN_BLKS];
__device__ uint2  g_tsh[NN * 32];    // ts = dinv*(X@W) in fp16: 4 halves/uint2, 128/node
__device__ float4 g_h[NN * 32];      // layer activations (fp32)
__device__ unsigned long long g_Wp1[64 * 128];  // W1 packed as (W[2t][c], W[2t+1][c])
__device__ unsigned long long g_Wp2[64 * 128];  // W2 packed

__device__ __forceinline__ void ffma2(unsigned long long& d, unsigned long long a,
                                      unsigned long long b) {
    asm("fma.rn.f32x2 %0, %1, %2, %0;" : "+l"(d) : "l"(a), "l"(b));
}

// ---------------- pack W1/W2 into k-pair layout ----------------
__global__ void k_packW(const float* __restrict__ W1, const float* __restrict__ W2) {
    int idx = blockIdx.x * blockDim.x + threadIdx.x;   // 0..16383
    int half = idx >> 13;
    int j = idx & 8191;
    int t = j >> 7;
    int c = j & 127;
    const float* W = half ? W2 : W1;
    unsigned lo = __float_as_uint(W[(2 * t) * 128 + c]);
    unsigned hi = __float_as_uint(W[(2 * t + 1) * 128 + c]);
    unsigned long long v = ((unsigned long long)hi << 32) | lo;
    if (half) g_Wp2[j] = v; else g_Wp1[j] = v;
}

// ---------------- degree histogram ----------------
__global__ void k_zero_deg() {
    int i = blockIdx.x * blockDim.x + threadIdx.x;   // int4 index
    if (i < NN / 4) ((int4*)g_deg)[i] = make_int4(0, 0, 0, 0);
}

// edge_index is int32 (JAX x64 disabled)
__global__ void k_hist(const int* __restrict__ ei) {
    int e4 = blockIdx.x * blockDim.x + threadIdx.x;
    if (e4 < EE / 4) {
        int4 d = ((const int4*)(ei + EE))[e4];
        atomicAdd(&g_deg[d.x], 1);
        atomicAdd(&g_deg[d.y], 1);
        atomicAdd(&g_deg[d.z], 1);
        atomicAdd(&g_deg[d.w], 1);
    }
}

// ---------------- hierarchical scan ----------------
__global__ void k_scan1() {
    __shared__ int ws[8];
    int tid = threadIdx.x, lane = tid & 31, wid = tid >> 5;
    int i4 = blockIdx.x * 256 + tid;
    int v = 0;
    if (i4 < NN / 4) {
        int4 d = ((const int4*)g_deg)[i4];
        v = d.x + d.y + d.z + d.w;
    }
    #pragma unroll
    for (int o = 16; o > 0; o >>= 1) v += __shfl_down_sync(0xffffffffu, v, o);
    if (lane == 0) ws[wid] = v;
    __syncthreads();
    if (wid == 0) {
        int s = (lane < 8) ? ws[lane] : 0;
        #pragma unroll
        for (int o = 4; o > 0; o >>= 1) s += __shfl_down_sync(0xffffffffu, s, o);
        if (lane == 0) g_bsum[blockIdx.x] = s;
    }
}

__global__ void k_scan2() {
    __shared__ int sh[64];
    int tid = threadIdx.x;   // 0..63
    sh[tid] = (tid < SCAN_BLKS) ? g_bsum[tid] : 0;
    __syncthreads();
    #pragma unroll
    for (int o = 1; o < 64; o <<= 1) {
        int v = (tid >= o) ? sh[tid - o] : 0;
        __syncthreads();
        sh[tid] += v;
        __syncthreads();
    }
    if (tid < SCAN_BLKS) g_boff[tid] = sh[tid] - g_bsum[tid];
    if (tid == 0) g_rowptr[NN] = EE;
}

__global__ void k_scan3() {
    __shared__ int ws[8];
    int tid = threadIdx.x, lane = tid & 31, wid = tid >> 5;
    int i4 = blockIdx.x * 256 + tid;
    int4 d = make_int4(0, 0, 0, 0);
    if (i4 < NN / 4) d = ((const int4*)g_deg)[i4];
    int tot = d.x + d.y + d.z + d.w;
    int incl = tot;
    #pragma unroll
    for (int o = 1; o < 32; o <<= 1) {
        int t = __shfl_up_sync(0xffffffffu, incl, o);
        if (lane >= o) incl += t;
    }
    if (lane == 31) ws[wid] = incl;
    __syncthreads();
    if (wid == 0) {
        int s = (lane < 8) ? ws[lane] : 0;
        int si = s;
        #pragma unroll
        for (int o = 1; o < 8; o <<= 1) {
            int t = __shfl_up_sync(0xffffffffu, si, o);
            if (lane >= o) si += t;
        }
        if (lane < 8) ws[lane] = si - s;
    }
    __syncthreads();
    int run = g_boff[blockIdx.x] + ws[wid] + incl - tot;
    if (i4 < NN / 4) {
        int p0 = run, p1 = p0 + d.x, p2 = p1 + d.y, p3 = p2 + d.z;
        ((int4*)g_rowptr)[i4] = make_int4(p0, p1, p2, p3);
        ((int4*)g_pos)[i4]    = make_int4(p0, p1, p2, p3);
        float4 dv;
        dv.x = rsqrtf((float)(d.x + 1));
        dv.y = rsqrtf((float)(d.y + 1));
        dv.z = rsqrtf((float)(d.z + 1));
        dv.w = rsqrtf((float)(d.w + 1));
        ((float4*)g_dinv)[i4] = dv;
    }
}

__global__ void k_fill(const int* __restrict__ ei) {
    int e4 = blockIdx.x * blockDim.x + threadIdx.x;
    if (e4 < EE / 4) {
        int4 d = ((const int4*)(ei + EE))[e4];
        int4 s = ((const int4*)ei)[e4];
        int p;
        p = atomicAdd(&g_pos[d.x], 1); g_col[p] = s.x;
        p = atomicAdd(&g_pos[d.y], 1); g_col[p] = s.y;
        p = atomicAdd(&g_pos[d.z], 1); g_col[p] = s.z;
        p = atomicAdd(&g_pos[d.w], 1); g_col[p] = s.w;
    }
}

// ---------------- GEMM (FFMA2): g_tsh = fp16( dinv[i] * (X[i,:] @ W) ) ----------------
template <int SEL>
__global__ void k_gemm(const float4* __restrict__ Xin) {
    __shared__ float4 Xs4[64 * 32];
    const float4* X4 = SEL ? (const float4*)g_h : Xin;
    const ulonglong2* Wp2 = (const ulonglong2*)(SEL ? g_Wp2 : g_Wp1);
    int tid  = threadIdx.x;
    int row0 = blockIdx.x * 64;

    #pragma unroll
    for (int j = 0; j < 8; j++) {
        int fi = tid + j * 256;
        int r  = fi >> 5;
        int kq = fi & 31;
        int gr = row0 + r;
        float4 v = make_float4(0.f, 0.f, 0.f, 0.f);
        if (gr < NN) v = X4[gr * 32 + kq];
        Xs4[fi] = v;
    }
    __syncthreads();

    int tx = tid & 31;   // col quad
    int ty = tid >> 5;   // row group
    unsigned long long acc2[8][4];
    #pragma unroll
    for (int i = 0; i < 8; i++)
        #pragma unroll
        for (int c = 0; c < 4; c++) acc2[i][c] = 0ull;

    const unsigned long long* Xs64 = (const unsigned long long*)Xs4;
    #pragma unroll 4
    for (int t = 0; t < 64; t++) {
        ulonglong2 wa = Wp2[t * 64 + 2 * tx];
        ulonglong2 wb = Wp2[t * 64 + 2 * tx + 1];
        #pragma unroll
        for (int i = 0; i < 8; i++) {
            unsigned long long xp = Xs64[(ty * 8 + i) * 64 + t];
            ffma2(acc2[i][0], xp, wa.x);
            ffma2(acc2[i][1], xp, wa.y);
            ffma2(acc2[i][2], xp, wb.x);
            ffma2(acc2[i][3], xp, wb.y);
        }
    }

    #pragma unroll
    for (int i = 0; i < 8; i++) {
        int gr = row0 + ty * 8 + i;
        if (gr < NN) {
            float di = g_dinv[gr];
            float r[4];
            #pragma unroll
            for (int c = 0; c < 4; c++) {
                unsigned long long v = acc2[i][c];
                float lo = __uint_as_float((unsigned)v);
                float hi = __uint_as_float((unsigned)(v >> 32));
                r[c] = (lo + hi) * di;
            }
            __half2 ha = __floats2half2_rn(r[0], r[1]);
            __half2 hb = __floats2half2_rn(r[2], r[3]);
            uint2 o;
            o.x = *reinterpret_cast<unsigned*>(&ha);
            o.y = *reinterpret_cast<unsigned*>(&hb);
            g_tsh[gr * 32 + tx] = o;
        }
    }
}

// ---------------- aggregation: g_h[i] = relu(dinv[i]*(sum ts[src] + ts[i]) + b) ----------------
__device__ __forceinline__ void acc_h4(float4& acc, uint2 u) {
    __half2 h0 = *reinterpret_cast<__half2*>(&u.x);
    __half2 h1 = *reinterpret_cast<__half2*>(&u.y);
    float2 f0 = __half22float2(h0);
    float2 f1 = __half22float2(h1);
    acc.x += f0.x; acc.y += f0.y; acc.z += f1.x; acc.w += f1.y;
}

__global__ void k_agg(const float4* __restrict__ b4) {
    int gtid = blockIdx.x * blockDim.x + threadIdx.x;
    int node = gtid >> 5;
    int lane = threadIdx.x & 31;
    if (node >= NN) return;
    float4 acc = make_float4(0.f, 0.f, 0.f, 0.f);
    acc_h4(acc, g_tsh[node * 32 + lane]);   // self term (already dinv-scaled)
    int s = g_rowptr[node], e = g_rowptr[node + 1];
    int j = s;
    for (; j + 3 < e; j += 4) {
        int c0 = g_col[j], c1 = g_col[j + 1], c2 = g_col[j + 2], c3 = g_col[j + 3];
        uint2 u0 = g_tsh[c0 * 32 + lane];
        uint2 u1 = g_tsh[c1 * 32 + lane];
        uint2 u2 = g_tsh[c2 * 32 + lane];
        uint2 u3 = g_tsh[c3 * 32 + lane];
        acc_h4(acc, u0); acc_h4(acc, u1); acc_h4(acc, u2); acc_h4(acc, u3);
    }
    for (; j < e; j++) {
        acc_h4(acc, g_tsh[g_col[j] * 32 + lane]);
    }
    float di = g_dinv[node];
    float4 bb = b4[lane];
    float4 o;
    o.x = fmaxf(fmaf(acc.x, di, bb.x), 0.f);
    o.y = fmaxf(fmaf(acc.y, di, bb.y), 0.f);
    o.z = fmaxf(fmaf(acc.z, di, bb.z), 0.f);
    o.w = fmaxf(fmaf(acc.w, di, bb.w), 0.f);
    g_h[node * 32 + lane] = o;
}

// ---------------- fused mean-pool + FC + head, one block per graph ----------------
__device__ __forceinline__ int lb_batch(const int* b, int v) {
    int lo = 0, hi = NN;
    while (lo < hi) {
        int m = (lo + hi) >> 1;
        if (b[m] < v) lo = m + 1; else hi = m;
    }
    return lo;
}

__global__ void k_poolhead(const int* __restrict__ batch,
                           const float* __restrict__ Wfc, const float* __restrict__ bfc,
                           const float* __restrict__ Wh, const float* __restrict__ bh,
                           float* __restrict__ out) {
    int g = blockIdx.x;
    int tid = threadIdx.x;   // 0..127
    __shared__ int s0, s1;
    __shared__ float pr[128];
    __shared__ float zs[128];
    if (tid == 0) {
        s0 = lb_batch(batch, g);
        s1 = lb_batch(batch, g + 1);
    }
    __syncthreads();
    int a = s0, bnd = s1;
    const float* h = (const float*)g_h;
    float acc = 0.f;
    int n = a;
    for (; n + 3 < bnd; n += 4) {
        acc += h[n * 128 + tid] + h[(n + 1) * 128 + tid]
             + h[(n + 2) * 128 + tid] + h[(n + 3) * 128 + tid];
    }
    for (; n < bnd; n++) acc += h[n * 128 + tid];
    float cnt = (float)(bnd - a);
    pr[tid] = acc / fmaxf(cnt, 1.f);
    __syncthreads();
    float z = bfc[tid];
    #pragma unroll 4
    for (int k = 0; k < 128; k++) z = fmaf(pr[k], Wfc[k * 128 + tid], z);
    zs[tid] = fmaxf(z, 0.f);
    __syncthreads();
    if (tid < TT * 2) {
        int t = tid >> 1, c = tid & 1;
        float s = bh[t * 2 + c];
        #pragma unroll 4
        for (int k = 0; k < 128; k++) s = fmaf(zs[k], Wh[t * 256 + k * 2 + c], s);
        out[t * (GG * 2) + g * 2 + c] = s;
    }
}

// ---------------- launch (kernels + capture-legal event fork/join only) ----------------
extern "C" void kernel_launch(void* const* d_in, const int* in_sizes, int n_in,
                              void* d_out, int out_size) {
    const float* x     = (const float*)d_in[0];
    const int*   ei    = (const int*)d_in[1];
    const int*   batch = (const int*)d_in[2];
    const float* W1    = (const float*)d_in[3];
    const float* b1    = (const float*)d_in[4];
    const float* W2    = (const float*)d_in[5];
    const float* b2    = (const float*)d_in[6];
    const float* Wfc   = (const float*)d_in[7];
    const float* bfc   = (const float*)d_in[8];
    const float* Wh    = (const float*)d_in[9];
    const float* bh    = (const float*)d_in[10];
    float* out = (float*)d_out;

    cudaStream_t s2 = g_ss.s2;

    // fork: CSR build on side stream, GEMM path on main stream
    cudaEventRecord(g_ss.evFork, 0);
    cudaStreamWaitEvent(s2, g_ss.evFork, 0);

    // --- side stream: CSR pipeline ---
    k_zero_deg<<<(NN / 4 + 255) / 256, 256, 0, s2>>>();
    k_hist<<<(EE / 4 + 255) / 256, 256, 0, s2>>>(ei);
    k_scan1<<<SCAN_BLKS, 256, 0, s2>>>();
    k_scan2<<<1, 64, 0, s2>>>();
    k_scan3<<<SCAN_BLKS, 256, 0, s2>>>();
    k_fill<<<(EE / 4 + 255) / 256, 256, 0, s2>>>(ei);
    cudaEventRecord(g_ss.evCsr, s2);

    // --- main stream: weight pack + layer-1 transform (independent of CSR,
    //     except the dinv epilogue scale; dinv is produced by k_scan3 — so the
    //     GEMM epilogue DOES need dinv. Keep GEMM1 on main stream but make it
    //     wait only on scan3, not fill: evCsr is after fill, so instead record
    //     a second event after scan3. Simpler correct ordering: GEMM1 waits on
    //     the full CSR event. To still get overlap, packW runs before the wait. ---
    k_packW<<<64, 256>>>(W1, W2);
    cudaStreamWaitEvent(0, g_ss.evCsr, 0);

    int gemm_blocks = (NN + 63) / 64;
    int agg_blocks  = (NN * 32 + 255) / 256;

    // layer 1
    k_gemm<0><<<gemm_blocks, 256>>>((const float4*)x);
    k_agg<<<agg_blocks, 256>>>((const float4*)b1);
    // layer 2
    k_gemm<1><<<gemm_blocks, 256>>>((const float4*)x);
    k_agg<<<agg_blocks, 256>>>((const float4*)b2);
    // fused pool + head
    k_poolhead<<<GG, 128>>>(batch, Wfc, bfc, Wh, bh, out);
}

// round 10
// speedup vs baseline: 1.0175x; 1.0175x over previous
#include <cuda_runtime.h>
#include <cuda_fp16.h>
#include <cuda_bf16.h>

#define NN 50000
#define EE 800000
#define FI 128
#define HH 128
#define GG 256
#define TT 4

#define SCAN_BLKS 49   // ceil(12500 int4 / 256)

// ---------------- streams/events (created once at program init) ----------------
struct SideStream {
    cudaStream_t s2;
    cudaEvent_t  evFork, evCsr;
    SideStream() {
        cudaStreamCreateWithFlags(&s2, cudaStreamNonBlocking);
        cudaEventCreateWithFlags(&evFork, cudaEventDisableTiming);
        cudaEventCreateWithFlags(&evCsr,  cudaEventDisableTiming);
    }
};
static SideStream g_ss;

// ---------------- scratch (device globals) ----------------
__device__ int    g_deg[NN];
__device__ int    g_rowptr[NN + 1];
__device__ int    g_pos[NN];
__device__ int    g_col[EE];
__device__ float  g_dinv[NN];
__device__ int    g_bsum[SCAN_BLKS];
__device__ int    g_boff[SCAN_BLKS];
__device__ uint2  g_tsh[NN * 32];    // ts = X@W in fp16 (UNSCALED): 4 halves/uint2
__device__ float4 g_h[NN * 32];      // layer activations (fp32)
__device__ unsigned long long g_Wp1[64 * 128];  // W1 packed as (W[2t][c], W[2t+1][c])
__device__ unsigned long long g_Wp2[64 * 128];  // W2 packed

__device__ __forceinline__ void ffma2(unsigned long long& d, unsigned long long a,
                                      unsigned long long b) {
    asm("fma.rn.f32x2 %0, %1, %2, %0;" : "+l"(d) : "l"(a), "l"(b));
}

// ---------------- pack W1/W2 into k-pair layout ----------------
__global__ void k_packW(const float* __restrict__ W1, const float* __restrict__ W2) {
    int idx = blockIdx.x * blockDim.x + threadIdx.x;   // 0..16383
    int half = idx >> 13;
    int j = idx & 8191;
    int t = j >> 7;
    int c = j & 127;
    const float* W = half ? W2 : W1;
    unsigned lo = __float_as_uint(W[(2 * t) * 128 + c]);
    unsigned hi = __float_as_uint(W[(2 * t + 1) * 128 + c]);
    unsigned long long v = ((unsigned long long)hi << 32) | lo;
    if (half) g_Wp2[j] = v; else g_Wp1[j] = v;
}

// ---------------- degree histogram ----------------
__global__ void k_zero_deg() {
    int i = blockIdx.x * blockDim.x + threadIdx.x;   // int4 index
    if (i < NN / 4) ((int4*)g_deg)[i] = make_int4(0, 0, 0, 0);
}

// edge_index is int32 (JAX x64 disabled)
__global__ void k_hist(const int* __restrict__ ei) {
    int e4 = blockIdx.x * blockDim.x + threadIdx.x;
    if (e4 < EE / 4) {
        int4 d = ((const int4*)(ei + EE))[e4];
        atomicAdd(&g_deg[d.x], 1);
        atomicAdd(&g_deg[d.y], 1);
        atomicAdd(&g_deg[d.z], 1);
        atomicAdd(&g_deg[d.w], 1);
    }
}

// ---------------- hierarchical scan ----------------
__global__ void k_scan1() {
    __shared__ int ws[8];
    int tid = threadIdx.x, lane = tid & 31, wid = tid >> 5;
    int i4 = blockIdx.x * 256 + tid;
    int v = 0;
    if (i4 < NN / 4) {
        int4 d = ((const int4*)g_deg)[i4];
        v = d.x + d.y + d.z + d.w;
    }
    #pragma unroll
    for (int o = 16; o > 0; o >>= 1) v += __shfl_down_sync(0xffffffffu, v, o);
    if (lane == 0) ws[wid] = v;
    __syncthreads();
    if (wid == 0) {
        int s = (lane < 8) ? ws[lane] : 0;
        #pragma unroll
        for (int o = 4; o > 0; o >>= 1) s += __shfl_down_sync(0xffffffffu, s, o);
        if (lane == 0) g_bsum[blockIdx.x] = s;
    }
}

__global__ void k_scan2() {
    __shared__ int sh[64];
    int tid = threadIdx.x;   // 0..63
    sh[tid] = (tid < SCAN_BLKS) ? g_bsum[tid] : 0;
    __syncthreads();
    #pragma unroll
    for (int o = 1; o < 64; o <<= 1) {
        int v = (tid >= o) ? sh[tid - o] : 0;
        __syncthreads();
        sh[tid] += v;
        __syncthreads();
    }
    if (tid < SCAN_BLKS) g_boff[tid] = sh[tid] - g_bsum[tid];
    if (tid == 0) g_rowptr[NN] = EE;
}

__global__ void k_scan3() {
    __shared__ int ws[8];
    int tid = threadIdx.x, lane = tid & 31, wid = tid >> 5;
    int i4 = blockIdx.x * 256 + tid;
    int4 d = make_int4(0, 0, 0, 0);
    if (i4 < NN / 4) d = ((const int4*)g_deg)[i4];
    int tot = d.x + d.y + d.z + d.w;
    int incl = tot;
    #pragma unroll
    for (int o = 1; o < 32; o <<= 1) {
        int t = __shfl_up_sync(0xffffffffu, incl, o);
        if (lane >= o) incl += t;
    }
    if (lane == 31) ws[wid] = incl;
    __syncthreads();
    if (wid == 0) {
        int s = (lane < 8) ? ws[lane] : 0;
        int si = s;
        #pragma unroll
        for (int o = 1; o < 8; o <<= 1) {
            int t = __shfl_up_sync(0xffffffffu, si, o);
            if (lane >= o) si += t;
        }
        if (lane < 8) ws[lane] = si - s;
    }
    __syncthreads();
    int run = g_boff[blockIdx.x] + ws[wid] + incl - tot;
    if (i4 < NN / 4) {
        int p0 = run, p1 = p0 + d.x, p2 = p1 + d.y, p3 = p2 + d.z;
        ((int4*)g_rowptr)[i4] = make_int4(p0, p1, p2, p3);
        ((int4*)g_pos)[i4]    = make_int4(p0, p1, p2, p3);
        float4 dv;
        dv.x = rsqrtf((float)(d.x + 1));
        dv.y = rsqrtf((float)(d.y + 1));
        dv.z = rsqrtf((float)(d.z + 1));
        dv.w = rsqrtf((float)(d.w + 1));
        ((float4*)g_dinv)[i4] = dv;
    }
}

__global__ void k_fill(const int* __restrict__ ei) {
    int e4 = blockIdx.x * blockDim.x + threadIdx.x;
    if (e4 < EE / 4) {
        int4 d = ((const int4*)(ei + EE))[e4];
        int4 s = ((const int4*)ei)[e4];
        int p;
        p = atomicAdd(&g_pos[d.x], 1); g_col[p] = s.x;
        p = atomicAdd(&g_pos[d.y], 1); g_col[p] = s.y;
        p = atomicAdd(&g_pos[d.z], 1); g_col[p] = s.z;
        p = atomicAdd(&g_pos[d.w], 1); g_col[p] = s.w;
    }
}

// ---------------- GEMM (FFMA2): g_tsh = fp16( X[i,:] @ W )  — NO dinv, NO CSR dep ----
template <int SEL>
__global__ void k_gemm(const float4* __restrict__ Xin) {
    __shared__ float4 Xs4[64 * 32];
    const float4* X4 = SEL ? (const float4*)g_h : Xin;
    const ulonglong2* Wp2 = (const ulonglong2*)(SEL ? g_Wp2 : g_Wp1);
    int tid  = threadIdx.x;
    int row0 = blockIdx.x * 64;

    #pragma unroll
    for (int j = 0; j < 8; j++) {
        int fi = tid + j * 256;
        int r  = fi >> 5;
        int kq = fi & 31;
        int gr = row0 + r;
        float4 v = make_float4(0.f, 0.f, 0.f, 0.f);
        if (gr < NN) v = X4[gr * 32 + kq];
        Xs4[fi] = v;
    }
    __syncthreads();

    int tx = tid & 31;   // col quad
    int ty = tid >> 5;   // row group
    unsigned long long acc2[8][4];
    #pragma unroll
    for (int i = 0; i < 8; i++)
        #pragma unroll
        for (int c = 0; c < 4; c++) acc2[i][c] = 0ull;

    const unsigned long long* Xs64 = (const unsigned long long*)Xs4;
    #pragma unroll 4
    for (int t = 0; t < 64; t++) {
        ulonglong2 wa = Wp2[t * 64 + 2 * tx];
        ulonglong2 wb = Wp2[t * 64 + 2 * tx + 1];
        #pragma unroll
        for (int i = 0; i < 8; i++) {
            unsigned long long xp = Xs64[(ty * 8 + i) * 64 + t];
            ffma2(acc2[i][0], xp, wa.x);
            ffma2(acc2[i][1], xp, wa.y);
            ffma2(acc2[i][2], xp, wb.x);
            ffma2(acc2[i][3], xp, wb.y);
        }
    }

    #pragma unroll
    for (int i = 0; i < 8; i++) {
        int gr = row0 + ty * 8 + i;
        if (gr < NN) {
            float r[4];
            #pragma unroll
            for (int c = 0; c < 4; c++) {
                unsigned long long v = acc2[i][c];
                float lo = __uint_as_float((unsigned)v);
                float hi = __uint_as_float((unsigned)(v >> 32));
                r[c] = lo + hi;
            }
            __half2 ha = __floats2half2_rn(r[0], r[1]);
            __half2 hb = __floats2half2_rn(r[2], r[3]);
            uint2 o;
            o.x = *reinterpret_cast<unsigned*>(&ha);
            o.y = *reinterpret_cast<unsigned*>(&hb);
            g_tsh[gr * 32 + tx] = o;
        }
    }
}

// ---------------- aggregation: h[i] = relu(dinv[i]*(sum dinv[c]*ts[c] + dinv[i]*ts[i]) + b) ----
__device__ __forceinline__ void acc_h4s(float4& acc, uint2 u, float s) {
    __half2 h0 = *reinterpret_cast<__half2*>(&u.x);
    __half2 h1 = *reinterpret_cast<__half2*>(&u.y);
    float2 f0 = __half22float2(h0);
    float2 f1 = __half22float2(h1);
    acc.x = fmaf(f0.x, s, acc.x); acc.y = fmaf(f0.y, s, acc.y);
    acc.z = fmaf(f1.x, s, acc.z); acc.w = fmaf(f1.y, s, acc.w);
}

__global__ void k_agg(const float4* __restrict__ b4) {
    int gtid = blockIdx.x * blockDim.x + threadIdx.x;
    int node = gtid >> 5;
    int lane = threadIdx.x & 31;
    if (node >= NN) return;
    float di = g_dinv[node];
    float4 acc = make_float4(0.f, 0.f, 0.f, 0.f);
    acc_h4s(acc, g_tsh[node * 32 + lane], di);   // self term
    int s = g_rowptr[node], e = g_rowptr[node + 1];
    int j = s;
    for (; j + 3 < e; j += 4) {
        int c0 = g_col[j], c1 = g_col[j + 1], c2 = g_col[j + 2], c3 = g_col[j + 3];
        float d0 = g_dinv[c0], d1 = g_dinv[c1], d2 = g_dinv[c2], d3 = g_dinv[c3];
        uint2 u0 = g_tsh[c0 * 32 + lane];
        uint2 u1 = g_tsh[c1 * 32 + lane];
        uint2 u2 = g_tsh[c2 * 32 + lane];
        uint2 u3 = g_tsh[c3 * 32 + lane];
        acc_h4s(acc, u0, d0); acc_h4s(acc, u1, d1);
        acc_h4s(acc, u2, d2); acc_h4s(acc, u3, d3);
    }
    for (; j < e; j++) {
        int c = g_col[j];
        acc_h4s(acc, g_tsh[c * 32 + lane], g_dinv[c]);
    }
    float4 bb = b4[lane];
    float4 o;
    o.x = fmaxf(fmaf(acc.x, di, bb.x), 0.f);
    o.y = fmaxf(fmaf(acc.y, di, bb.y), 0.f);
    o.z = fmaxf(fmaf(acc.z, di, bb.z), 0.f);
    o.w = fmaxf(fmaf(acc.w, di, bb.w), 0.f);
    g_h[node * 32 + lane] = o;
}

// ---------------- fused mean-pool + FC + head ----------------
__device__ __forceinline__ int lb_batch(const int* b, int v) {
    int lo = 0, hi = NN;
    while (lo < hi) {
        int m = (lo + hi) >> 1;
        if (b[m] < v) lo = m + 1; else hi = m;
    }
    return lo;
}

__global__ void k_poolhead(const int* __restrict__ batch,
                           const float* __restrict__ Wfc, const float* __restrict__ bfc,
                           const float* __restrict__ Wh, const float* __restrict__ bh,
                           float* __restrict__ out) {
    int g = blockIdx.x;
    int tid = threadIdx.x;   // 0..127
    __shared__ int s0, s1;
    __shared__ float pr[128];
    __shared__ float zs[128];
    if (tid == 0) {
        s0 = lb_batch(batch, g);
        s1 = lb_batch(batch, g + 1);
    }
    __syncthreads();
    int a = s0, bnd = s1;
    const float* h = (const float*)g_h;
    float acc = 0.f;
    int n = a;
    for (; n + 3 < bnd; n += 4) {
        acc += h[n * 128 + tid] + h[(n + 1) * 128 + tid]
             + h[(n + 2) * 128 + tid] + h[(n + 3) * 128 + tid];
    }
    for (; n < bnd; n++) acc += h[n * 128 + tid];
    float cnt = (float)(bnd - a);
    pr[tid] = acc / fmaxf(cnt, 1.f);
    __syncthreads();
    float z = bfc[tid];
    #pragma unroll 4
    for (int k = 0; k < 128; k++) z = fmaf(pr[k], Wfc[k * 128 + tid], z);
    zs[tid] = fmaxf(z, 0.f);
    __syncthreads();
    if (tid < TT * 2) {
        int t = tid >> 1, c = tid & 1;
        float s = bh[t * 2 + c];
        #pragma unroll 4
        for (int k = 0; k < 128; k++) s = fmaf(zs[k], Wh[t * 256 + k * 2 + c], s);
        out[t * (GG * 2) + g * 2 + c] = s;
    }
}

// ---------------- launch: true fork-join (GEMM1 independent of CSR) ----------------
extern "C" void kernel_launch(void* const* d_in, const int* in_sizes, int n_in,
                              void* d_out, int out_size) {
    const float* x     = (const float*)d_in[0];
    const int*   ei    = (const int*)d_in[1];
    const int*   batch = (const int*)d_in[2];
    const float* W1    = (const float*)d_in[3];
    const float* b1    = (const float*)d_in[4];
    const float* W2    = (const float*)d_in[5];
    const float* b2    = (const float*)d_in[6];
    const float* Wfc   = (const float*)d_in[7];
    const float* bfc   = (const float*)d_in[8];
    const float* Wh    = (const float*)d_in[9];
    const float* bh    = (const float*)d_in[10];
    float* out = (float*)d_out;

    cudaStream_t s2 = g_ss.s2;

    // fork
    cudaEventRecord(g_ss.evFork, 0);
    cudaStreamWaitEvent(s2, g_ss.evFork, 0);

    // side stream: full CSR pipeline (deg, scan, fill, dinv)
    k_zero_deg<<<(NN / 4 + 255) / 256, 256, 0, s2>>>();
    k_hist<<<(EE / 4 + 255) / 256, 256, 0, s2>>>(ei);
    k_scan1<<<SCAN_BLKS, 256, 0, s2>>>();
    k_scan2<<<1, 64, 0, s2>>>();
    k_scan3<<<SCAN_BLKS, 256, 0, s2>>>();
    k_fill<<<(EE / 4 + 255) / 256, 256, 0, s2>>>(ei);
    cudaEventRecord(g_ss.evCsr, s2);

    int gemm_blocks = (NN + 63) / 64;
    int agg_blocks  = (NN * 32 + 255) / 256;

    // main stream: packW + GEMM1 run CONCURRENTLY with the CSR build
    k_packW<<<64, 256>>>(W1, W2);
    k_gemm<0><<<gemm_blocks, 256>>>((const float4*)x);

    // join: aggregation needs CSR + dinv + ts
    cudaStreamWaitEvent(0, g_ss.evCsr, 0);
    k_agg<<<agg_blocks, 256>>>((const float4*)b1);
    // layer 2
    k_gemm<1><<<gemm_blocks, 256>>>((const float4*)x);
    k_agg<<<agg_blocks, 256>>>((const float4*)b2);
    // fused pool + head
    k_poolhead<<<GG, 128>>>(batch, Wfc, bfc, Wh, bh, out);
}